// round 1
// baseline (speedup 1.0000x reference)
#include <cuda_runtime.h>
#include <cstdint>
#include <cstddef>

// ---------------------------------------------------------------------------
// Self-attention: B=8, T=2048, D=1024, FF=1024, fp32.
//   Q = X@Wq^T + bq ; K = X@Wk^T + bk ; V = X@Wv^T + bv
//   S = softmax( (Q@K^T) * 0.03125 ) ; O = S@V
// Strategy: tf32 mma.sync GEMMs (fp32 accum, cvt.rna conversion), scratch in
// __device__ globals, 5 graph-capturable launches.
// ---------------------------------------------------------------------------

#define B_ 8
#define T_ 2048
#define F_ 1024

// Scratch (static device allocations; allowed per harness rules)
__device__ float g_Q [(size_t)B_ * T_ * F_];
__device__ float g_K [(size_t)B_ * T_ * F_];
__device__ float g_V [(size_t)B_ * T_ * F_];
__device__ float g_VT[(size_t)B_ * T_ * F_];
__device__ float g_S [(size_t)B_ * T_ * T_];

__device__ __forceinline__ uint32_t f2tf(float f) {
    uint32_t r;
    asm("cvt.rna.tf32.f32 %0, %1;" : "=r"(r) : "f"(f));
    return r;
}

__device__ __forceinline__ void cpa16(uint32_t dst_smem, const void* src) {
    asm volatile("cp.async.cg.shared.global [%0], [%1], 16;" :: "r"(dst_smem), "l"(src));
}

#define MMA_TF32(d, a, b)                                                     \
    asm volatile(                                                             \
        "mma.sync.aligned.m16n8k8.row.col.f32.tf32.tf32.f32 "                 \
        "{%0,%1,%2,%3},{%4,%5,%6,%7},{%8,%9},{%0,%1,%2,%3};"                  \
        : "+f"(d[0]), "+f"(d[1]), "+f"(d[2]), "+f"(d[3])                      \
        : "r"(a[0]), "r"(a[1]), "r"(a[2]), "r"(a[3]), "r"(b[0]), "r"(b[1]))

// ---------------------------------------------------------------------------
// Generic GEMM: C[z][m][n] = alpha * sum_k A[z][m][k] * B[z][n][k] (+ bias[n])
// A: [M,K] row-major, B: [N,K] row-major (i.e. computes A @ B^T).
// Tiles: BM=BN=128, BK=16. 256 threads = 8 warps in 2x4 grid, warp tile 64x32.
// M, N must be multiples of 128; K multiple of 16 (true for every call here).
// ---------------------------------------------------------------------------
template <bool HAS_BIAS>
__global__ __launch_bounds__(256, 2) void gemm_tf32(
    const float* __restrict__ A, const float* __restrict__ B,
    float* __restrict__ C, const float* __restrict__ bias,
    int N, int K,
    long long bsA, long long bsB, long long bsC, float alpha)
{
    __shared__ float sA[2][128][20];   // padded stride 20: conflict-free frag reads
    __shared__ float sB[2][128][20];

    const int tid  = threadIdx.x;
    const int warp = tid >> 5, lane = tid & 31;
    const int wm   = warp >> 2;        // 0..1 : warp-row (64 rows each)
    const int wn   = warp & 3;         // 0..3 : warp-col (32 cols each)
    const int gid  = lane >> 2, tig = lane & 3;

    const int m0 = blockIdx.y * 128;
    const int n0 = blockIdx.x * 128;

    const float* Ab = A + (size_t)blockIdx.z * bsA;
    const float* Bb = B + (size_t)blockIdx.z * bsB;
    float*       Cb = C + (size_t)blockIdx.z * bsC;

    // Per-thread global->shared copy coords: 512 16B-chunks per tile, 2/thread
    const int lr0 = tid >> 2;          // rows 0..63
    const int lr1 = lr0 + 64;          // rows 64..127
    const int lkc = (tid & 3) * 4;     // col within 16-wide k-slab

    float acc[4][4][4];
#pragma unroll
    for (int i = 0; i < 4; i++)
#pragma unroll
        for (int j = 0; j < 4; j++)
#pragma unroll
            for (int c = 0; c < 4; c++) acc[i][j][c] = 0.0f;

    const int KT = K >> 4;

    auto issue = [&](int kt, int st) {
        const int kb = (kt << 4) + lkc;
        cpa16((uint32_t)__cvta_generic_to_shared(&sA[st][lr0][lkc]),
              Ab + (size_t)(m0 + lr0) * K + kb);
        cpa16((uint32_t)__cvta_generic_to_shared(&sA[st][lr1][lkc]),
              Ab + (size_t)(m0 + lr1) * K + kb);
        cpa16((uint32_t)__cvta_generic_to_shared(&sB[st][lr0][lkc]),
              Bb + (size_t)(n0 + lr0) * K + kb);
        cpa16((uint32_t)__cvta_generic_to_shared(&sB[st][lr1][lkc]),
              Bb + (size_t)(n0 + lr1) * K + kb);
        asm volatile("cp.async.commit_group;");
    };

    issue(0, 0);

    for (int kt = 0; kt < KT; ++kt) {
        const int st = kt & 1;
        if (kt + 1 < KT) {
            issue(kt + 1, st ^ 1);
            asm volatile("cp.async.wait_group 1;");
        } else {
            asm volatile("cp.async.wait_group 0;");
        }
        __syncthreads();

#pragma unroll
        for (int ks = 0; ks < 2; ++ks) {
            const int kk = ks * 8;
            uint32_t af[4][4], bf[4][2];
#pragma unroll
            for (int im = 0; im < 4; im++) {
                const int r = wm * 64 + im * 16 + gid;
                af[im][0] = f2tf(sA[st][r][kk + tig]);
                af[im][1] = f2tf(sA[st][r + 8][kk + tig]);
                af[im][2] = f2tf(sA[st][r][kk + tig + 4]);
                af[im][3] = f2tf(sA[st][r + 8][kk + tig + 4]);
            }
#pragma unroll
            for (int in_ = 0; in_ < 4; in_++) {
                const int rn = wn * 32 + in_ * 8 + gid;
                bf[in_][0] = f2tf(sB[st][rn][kk + tig]);
                bf[in_][1] = f2tf(sB[st][rn][kk + tig + 4]);
            }
#pragma unroll
            for (int im = 0; im < 4; im++)
#pragma unroll
                for (int in_ = 0; in_ < 4; in_++)
                    MMA_TF32(acc[im][in_], af[im], bf[in_]);
        }
        __syncthreads();
    }

    // Epilogue
#pragma unroll
    for (int im = 0; im < 4; im++) {
        const int r = m0 + wm * 64 + im * 16 + gid;
#pragma unroll
        for (int in_ = 0; in_ < 4; in_++) {
            const int cc = n0 + wn * 32 + in_ * 8 + 2 * tig;
            float b0 = 0.0f, b1 = 0.0f;
            if (HAS_BIAS) { b0 = bias[cc]; b1 = bias[cc + 1]; }
            float2 v0 = make_float2(alpha * acc[im][in_][0] + b0,
                                    alpha * acc[im][in_][1] + b1);
            float2 v1 = make_float2(alpha * acc[im][in_][2] + b0,
                                    alpha * acc[im][in_][3] + b1);
            *(float2*)(Cb + (size_t)r * N + cc)       = v0;
            *(float2*)(Cb + (size_t)(r + 8) * N + cc) = v1;
        }
    }
}

// ---------------------------------------------------------------------------
// Batched transpose: V [B][T][F] -> VT [B][F][T]
// ---------------------------------------------------------------------------
__global__ void transpose_k(const float* __restrict__ in, float* __restrict__ out)
{
    __shared__ float t[32][33];
    const int z  = blockIdx.z;
    const int s0 = blockIdx.x * 32;    // along T (2048)
    const int f0 = blockIdx.y * 32;    // along F (1024)
    const float* ib = in  + (size_t)z * T_ * F_;
    float*       ob = out + (size_t)z * T_ * F_;
    const int tx = threadIdx.x, ty = threadIdx.y;
#pragma unroll
    for (int i = 0; i < 32; i += 8)
        t[ty + i][tx] = ib[(size_t)(s0 + ty + i) * F_ + f0 + tx];
    __syncthreads();
#pragma unroll
    for (int i = 0; i < 32; i += 8)
        ob[(size_t)(f0 + ty + i) * T_ + s0 + tx] = t[tx][ty + i];
}

// ---------------------------------------------------------------------------
// Row softmax over rows of length 2048, values kept in registers (1 R/W pass)
// grid: (T_, B_), block: 256
// ---------------------------------------------------------------------------
__global__ __launch_bounds__(256) void softmax2048(float* __restrict__ S)
{
    float* p = S + ((size_t)blockIdx.y * T_ + blockIdx.x) * T_;
    const int tid = threadIdx.x;
    __shared__ float rmax[8], rsum[8];

    float v[8];
    float m = -3.0e38f;
#pragma unroll
    for (int i = 0; i < 8; i++) { v[i] = p[tid + (i << 8)]; m = fmaxf(m, v[i]); }
#pragma unroll
    for (int o = 16; o > 0; o >>= 1) m = fmaxf(m, __shfl_xor_sync(0xffffffffu, m, o));
    if ((tid & 31) == 0) rmax[tid >> 5] = m;
    __syncthreads();
    float bm = rmax[0];
#pragma unroll
    for (int i = 1; i < 8; i++) bm = fmaxf(bm, rmax[i]);

    float s = 0.0f;
#pragma unroll
    for (int i = 0; i < 8; i++) { v[i] = __expf(v[i] - bm); s += v[i]; }
#pragma unroll
    for (int o = 16; o > 0; o >>= 1) s += __shfl_xor_sync(0xffffffffu, s, o);
    if ((tid & 31) == 0) rsum[tid >> 5] = s;
    __syncthreads();
    float bs = 0.0f;
#pragma unroll
    for (int i = 0; i < 8; i++) bs += rsum[i];

    const float inv = 1.0f / bs;
#pragma unroll
    for (int i = 0; i < 8; i++) p[tid + (i << 8)] = v[i] * inv;
}

// ---------------------------------------------------------------------------
extern "C" void kernel_launch(void* const* d_in, const int* in_sizes, int n_in,
                              void* d_out, int out_size)
{
    const float* X  = (const float*)d_in[0];
    const float* Wq = (const float*)d_in[1];
    const float* bq = (const float*)d_in[2];
    const float* Wk = (const float*)d_in[3];
    const float* bk = (const float*)d_in[4];
    const float* Wv = (const float*)d_in[5];
    const float* bv = (const float*)d_in[6];
    float* O = (float*)d_out;

    float *Q, *K, *V, *VT, *S;
    cudaGetSymbolAddress((void**)&Q,  g_Q);
    cudaGetSymbolAddress((void**)&K,  g_K);
    cudaGetSymbolAddress((void**)&V,  g_V);
    cudaGetSymbolAddress((void**)&VT, g_VT);
    cudaGetSymbolAddress((void**)&S,  g_S);

    const dim3 blk(256);

    // QKV projections: C[16384,1024] = X[16384,1024] @ W^T + b
    gemm_tf32<true><<<dim3(8, 128, 1), blk>>>(X, Wq, Q, bq, F_, F_, 0, 0, 0, 1.0f);
    gemm_tf32<true><<<dim3(8, 128, 1), blk>>>(X, Wk, K, bk, F_, F_, 0, 0, 0, 1.0f);
    gemm_tf32<true><<<dim3(8, 128, 1), blk>>>(X, Wv, V, bv, F_, F_, 0, 0, 0, 1.0f);

    // V -> VT for the PV GEMM (keeps single A@B^T kernel convention)
    transpose_k<<<dim3(T_ / 32, F_ / 32, B_), dim3(32, 8)>>>(V, VT);

    // scores: S[z] = (Q[z] @ K[z]^T) * 1/32
    gemm_tf32<false><<<dim3(16, 16, B_), blk>>>(
        Q, K, S, nullptr, T_, F_,
        (long long)T_ * F_, (long long)T_ * F_, (long long)T_ * T_, 0.03125f);

    // softmax rows
    softmax2048<<<dim3(T_, B_), blk>>>(S);

    // O[z] = S[z] @ V[z]  (= S @ VT^T)
    gemm_tf32<false><<<dim3(8, 16, B_), blk>>>(
        S, VT, O, nullptr, F_, T_,
        (long long)T_ * T_, (long long)F_ * T_, (long long)T_ * F_, 1.0f);
}

// round 2
// speedup vs baseline: 1.0910x; 1.0910x over previous
#include <cuda_runtime.h>
#include <cstdint>
#include <cstddef>

// ---------------------------------------------------------------------------
// Self-attention: B=8, T=2048, D=1024, FF=1024, fp32.
// tf32 mma.sync GEMMs with producer-side rounding (no cvt in hot loop),
// ldmatrix.x4 fragment loads, 4-stage cp.async pipeline.
// ---------------------------------------------------------------------------

#define B_ 8
#define T_ 2048
#define F_ 1024

__device__ float g_Xr[(size_t)B_ * T_ * F_];
__device__ float g_Wq[(size_t)F_ * F_];
__device__ float g_Wk[(size_t)F_ * F_];
__device__ float g_Wv[(size_t)F_ * F_];
__device__ float g_Q [(size_t)B_ * T_ * F_];
__device__ float g_K [(size_t)B_ * T_ * F_];
__device__ float g_V [(size_t)B_ * T_ * F_];
__device__ float g_VT[(size_t)B_ * T_ * F_];
__device__ float g_S [(size_t)B_ * T_ * T_];

__device__ __forceinline__ uint32_t f2tf(float f) {
    uint32_t r;
    asm("cvt.rna.tf32.f32 %0, %1;" : "=r"(r) : "f"(f));
    return r;
}
__device__ __forceinline__ float roundtf(float f) { return __uint_as_float(f2tf(f)); }

__device__ __forceinline__ void cpa16(uint32_t dst_smem, const void* src) {
    asm volatile("cp.async.cg.shared.global [%0], [%1], 16;" :: "r"(dst_smem), "l"(src));
}

#define MMA_TF32(d, a, b)                                                     \
    asm volatile(                                                             \
        "mma.sync.aligned.m16n8k8.row.col.f32.tf32.tf32.f32 "                 \
        "{%0,%1,%2,%3},{%4,%5,%6,%7},{%8,%9},{%0,%1,%2,%3};"                  \
        : "+f"(d[0]), "+f"(d[1]), "+f"(d[2]), "+f"(d[3])                      \
        : "r"(a[0]), "r"(a[1]), "r"(a[2]), "r"(a[3]), "r"(b[0]), "r"(b[1]))

#define LDSM4(r0, r1, r2, r3, addr)                                           \
    asm volatile("ldmatrix.sync.aligned.m8n8.x4.shared.b16 {%0,%1,%2,%3},[%4];" \
        : "=r"(r0), "=r"(r1), "=r"(r2), "=r"(r3) : "r"(addr))

// ---------------------------------------------------------------------------
// tf32-round a float array (float4 grid-stride-free: exact grid)
// ---------------------------------------------------------------------------
__global__ void round_pass(const float4* __restrict__ in, float4* __restrict__ out)
{
    const int i = blockIdx.x * blockDim.x + threadIdx.x;
    float4 v = in[i];
    v.x = roundtf(v.x); v.y = roundtf(v.y);
    v.z = roundtf(v.z); v.w = roundtf(v.w);
    out[i] = v;
}

// ---------------------------------------------------------------------------
// GEMM: C[z] = alpha * A[z] @ B[z]^T (+ bias), A:[M,K] B:[N,K] row-major.
// Inputs must be pre-rounded to tf32 values. BM=BN=128, BK=16, 4 stages.
// 256 thr = 8 warps (2x4), warp tile 64x32. ldmatrix fragment loads.
// ---------------------------------------------------------------------------
#define PAD 20
#define STG_FLT (128 * PAD)
#define STG_B   (STG_FLT * 4)
#define NSTAGE  4
#define GEMM_SMEM (2 * NSTAGE * STG_B)   // 81920 bytes

template <bool HAS_BIAS, bool ROUND_OUT>
__global__ __launch_bounds__(256, 2) void gemm_tf32(
    const float* __restrict__ A, const float* __restrict__ B,
    float* __restrict__ C, const float* __restrict__ bias,
    int N, int K,
    long long bsA, long long bsB, long long bsC, float alpha)
{
    extern __shared__ float smem[];
    float* sA = smem;
    float* sB = smem + NSTAGE * STG_FLT;

    const int tid  = threadIdx.x;
    const int warp = tid >> 5, lane = tid & 31;
    const int wm   = warp >> 2;
    const int wn   = warp & 3;
    const int gid  = lane >> 2, tig = lane & 3;

    const int m0 = blockIdx.y * 128;
    const int n0 = blockIdx.x * 128;

    const float* Ab = A + (size_t)blockIdx.z * bsA;
    const float* Bb = B + (size_t)blockIdx.z * bsB;
    float*       Cb = C + (size_t)blockIdx.z * bsC;

    // cp.async coords: 2 x 16B chunks per array per thread
    const int lr0 = tid >> 2;
    const int lr1 = lr0 + 64;
    const int lkc = (tid & 3) * 4;

    // ldmatrix per-lane base addresses (byte offsets into stage 0)
    const uint32_t smem_u32 = (uint32_t)__cvta_generic_to_shared(smem);
    const int arow = wm * 64 + (lane & 7) + ((lane >> 3) & 1) * 8;
    const int acol = (lane >> 4) * 4;
    const uint32_t aBase = smem_u32 + (uint32_t)(arow * PAD + acol) * 4u;
    const int brow = wn * 32 + (lane & 7) + (lane >> 4) * 8;
    const int bcol = ((lane >> 3) & 1) * 4;
    const uint32_t bBase = smem_u32 + (uint32_t)(NSTAGE * STG_FLT) * 4u
                         + (uint32_t)(brow * PAD + bcol) * 4u;

    float acc[4][4][4];
#pragma unroll
    for (int i = 0; i < 4; i++)
#pragma unroll
        for (int j = 0; j < 4; j++)
#pragma unroll
            for (int c = 0; c < 4; c++) acc[i][j][c] = 0.0f;

    const int KT = K >> 4;

    auto issue = [&](int kt, int st) {
        const int kb = (kt << 4) + lkc;
        float* pA = sA + st * STG_FLT;
        float* pB = sB + st * STG_FLT;
        cpa16((uint32_t)__cvta_generic_to_shared(pA + lr0 * PAD + lkc),
              Ab + (size_t)(m0 + lr0) * K + kb);
        cpa16((uint32_t)__cvta_generic_to_shared(pA + lr1 * PAD + lkc),
              Ab + (size_t)(m0 + lr1) * K + kb);
        cpa16((uint32_t)__cvta_generic_to_shared(pB + lr0 * PAD + lkc),
              Bb + (size_t)(n0 + lr0) * K + kb);
        cpa16((uint32_t)__cvta_generic_to_shared(pB + lr1 * PAD + lkc),
              Bb + (size_t)(n0 + lr1) * K + kb);
        asm volatile("cp.async.commit_group;");
    };

    issue(0, 0);
    issue(1, 1);
    issue(2, 2);

    for (int kt = 0; kt < KT; ++kt) {
        const int st = kt & (NSTAGE - 1);
        const int rem = KT - 1 - kt;
        if (rem >= 2)      asm volatile("cp.async.wait_group 2;");
        else if (rem == 1) asm volatile("cp.async.wait_group 1;");
        else               asm volatile("cp.async.wait_group 0;");
        __syncthreads();

        if (kt + 3 < KT) issue(kt + 3, (kt + 3) & (NSTAGE - 1));

        const uint32_t aSt = aBase + st * STG_B;
        const uint32_t bSt = bBase + st * STG_B;

#pragma unroll
        for (int ks = 0; ks < 2; ++ks) {
            const uint32_t ko = ks * 32;   // 8 floats
            uint32_t af[4][4], bf[4][2];
#pragma unroll
            for (int im = 0; im < 4; im++)
                LDSM4(af[im][0], af[im][1], af[im][2], af[im][3],
                      aSt + im * (16 * PAD * 4) + ko);
#pragma unroll
            for (int p = 0; p < 2; p++)
                LDSM4(bf[2 * p][0], bf[2 * p][1], bf[2 * p + 1][0], bf[2 * p + 1][1],
                      bSt + p * (16 * PAD * 4) + ko);
#pragma unroll
            for (int im = 0; im < 4; im++)
#pragma unroll
                for (int in_ = 0; in_ < 4; in_++)
                    MMA_TF32(acc[im][in_], af[im], bf[in_]);
        }
        __syncthreads();
    }

    // Epilogue
#pragma unroll
    for (int im = 0; im < 4; im++) {
        const int r = m0 + wm * 64 + im * 16 + gid;
#pragma unroll
        for (int in_ = 0; in_ < 4; in_++) {
            const int cc = n0 + wn * 32 + in_ * 8 + 2 * tig;
            float b0 = 0.0f, b1 = 0.0f;
            if (HAS_BIAS) { b0 = bias[cc]; b1 = bias[cc + 1]; }
            float o00 = alpha * acc[im][in_][0] + b0;
            float o01 = alpha * acc[im][in_][1] + b1;
            float o10 = alpha * acc[im][in_][2] + b0;
            float o11 = alpha * acc[im][in_][3] + b1;
            if (ROUND_OUT) {
                o00 = roundtf(o00); o01 = roundtf(o01);
                o10 = roundtf(o10); o11 = roundtf(o11);
            }
            *(float2*)(Cb + (size_t)r * N + cc)       = make_float2(o00, o01);
            *(float2*)(Cb + (size_t)(r + 8) * N + cc) = make_float2(o10, o11);
        }
    }
}

// ---------------------------------------------------------------------------
// Batched transpose: V [B][T][F] -> VT [B][F][T]
// ---------------------------------------------------------------------------
__global__ void transpose_k(const float* __restrict__ in, float* __restrict__ out)
{
    __shared__ float t[32][33];
    const int z  = blockIdx.z;
    const int s0 = blockIdx.x * 32;
    const int f0 = blockIdx.y * 32;
    const float* ib = in  + (size_t)z * T_ * F_;
    float*       ob = out + (size_t)z * T_ * F_;
    const int tx = threadIdx.x, ty = threadIdx.y;
#pragma unroll
    for (int i = 0; i < 32; i += 8)
        t[ty + i][tx] = ib[(size_t)(s0 + ty + i) * F_ + f0 + tx];
    __syncthreads();
#pragma unroll
    for (int i = 0; i < 32; i += 8)
        ob[(size_t)(f0 + ty + i) * T_ + s0 + tx] = t[tx][ty + i];
}

// ---------------------------------------------------------------------------
// Row softmax, 2048 cols in registers; output rounded to tf32 values.
// ---------------------------------------------------------------------------
__global__ __launch_bounds__(256) void softmax2048(float* __restrict__ S)
{
    float* p = S + ((size_t)blockIdx.y * T_ + blockIdx.x) * T_;
    const int tid = threadIdx.x;
    __shared__ float rmax[8], rsum[8];

    float v[8];
    float m = -3.0e38f;
#pragma unroll
    for (int i = 0; i < 8; i++) { v[i] = p[tid + (i << 8)]; m = fmaxf(m, v[i]); }
#pragma unroll
    for (int o = 16; o > 0; o >>= 1) m = fmaxf(m, __shfl_xor_sync(0xffffffffu, m, o));
    if ((tid & 31) == 0) rmax[tid >> 5] = m;
    __syncthreads();
    float bm = rmax[0];
#pragma unroll
    for (int i = 1; i < 8; i++) bm = fmaxf(bm, rmax[i]);

    float s = 0.0f;
#pragma unroll
    for (int i = 0; i < 8; i++) { v[i] = __expf(v[i] - bm); s += v[i]; }
#pragma unroll
    for (int o = 16; o > 0; o >>= 1) s += __shfl_xor_sync(0xffffffffu, s, o);
    if ((tid & 31) == 0) rsum[tid >> 5] = s;
    __syncthreads();
    float bs = 0.0f;
#pragma unroll
    for (int i = 0; i < 8; i++) bs += rsum[i];

    const float inv = 1.0f / bs;
#pragma unroll
    for (int i = 0; i < 8; i++) p[tid + (i << 8)] = roundtf(v[i] * inv);
}

// ---------------------------------------------------------------------------
extern "C" void kernel_launch(void* const* d_in, const int* in_sizes, int n_in,
                              void* d_out, int out_size)
{
    const float* X  = (const float*)d_in[0];
    const float* Wq = (const float*)d_in[1];
    const float* bq = (const float*)d_in[2];
    const float* Wk = (const float*)d_in[3];
    const float* bk = (const float*)d_in[4];
    const float* Wv = (const float*)d_in[5];
    const float* bv = (const float*)d_in[6];
    float* O = (float*)d_out;

    float *Xr, *Wqr, *Wkr, *Wvr, *Q, *K, *V, *VT, *S;
    cudaGetSymbolAddress((void**)&Xr,  g_Xr);
    cudaGetSymbolAddress((void**)&Wqr, g_Wq);
    cudaGetSymbolAddress((void**)&Wkr, g_Wk);
    cudaGetSymbolAddress((void**)&Wvr, g_Wv);
    cudaGetSymbolAddress((void**)&Q,   g_Q);
    cudaGetSymbolAddress((void**)&K,   g_K);
    cudaGetSymbolAddress((void**)&V,   g_V);
    cudaGetSymbolAddress((void**)&VT,  g_VT);
    cudaGetSymbolAddress((void**)&S,   g_S);

    cudaFuncSetAttribute(gemm_tf32<true, true>,
                         cudaFuncAttributeMaxDynamicSharedMemorySize, GEMM_SMEM);
    cudaFuncSetAttribute(gemm_tf32<false, false>,
                         cudaFuncAttributeMaxDynamicSharedMemorySize, GEMM_SMEM);

    const dim3 blk(256);

    // tf32-round inputs once (X: 16.7M elts, W: 1M each)
    round_pass<<<(B_ * T_ * F_ / 4) / 256, 256>>>((const float4*)X,  (float4*)Xr);
    round_pass<<<(F_ * F_ / 4) / 256,     256>>>((const float4*)Wq, (float4*)Wqr);
    round_pass<<<(F_ * F_ / 4) / 256,     256>>>((const float4*)Wk, (float4*)Wkr);
    round_pass<<<(F_ * F_ / 4) / 256,     256>>>((const float4*)Wv, (float4*)Wvr);

    // QKV projections (outputs rounded to tf32 values)
    gemm_tf32<true, true><<<dim3(8, 128, 1), blk, GEMM_SMEM>>>(
        Xr, Wqr, Q, bq, F_, F_, 0, 0, 0, 1.0f);
    gemm_tf32<true, true><<<dim3(8, 128, 1), blk, GEMM_SMEM>>>(
        Xr, Wkr, K, bk, F_, F_, 0, 0, 0, 1.0f);
    gemm_tf32<true, true><<<dim3(8, 128, 1), blk, GEMM_SMEM>>>(
        Xr, Wvr, V, bv, F_, F_, 0, 0, 0, 1.0f);

    // V -> VT (values already tf32-rounded)
    transpose_k<<<dim3(T_ / 32, F_ / 32, B_), dim3(32, 8)>>>(V, VT);

    // scores (fp32 out; softmax rounds)
    gemm_tf32<false, false><<<dim3(16, 16, B_), blk, GEMM_SMEM>>>(
        Q, K, S, nullptr, T_, F_,
        (long long)T_ * F_, (long long)T_ * F_, (long long)T_ * T_, 0.03125f);

    softmax2048<<<dim3(T_, B_), blk>>>(S);

    // O = S @ VT^T (full fp32 epilogue)
    gemm_tf32<false, false><<<dim3(8, 16, B_), blk, GEMM_SMEM>>>(
        S, VT, O, nullptr, F_, T_,
        (long long)T_ * T_, (long long)F_ * T_, (long long)T_ * F_, 1.0f);
}

// round 4
// speedup vs baseline: 2.0289x; 1.8597x over previous
#include <cuda_runtime.h>
#include <cuda_fp16.h>
#include <cstdint>
#include <cstddef>

// ---------------------------------------------------------------------------
// Self-attention B=8,T=2048,D=1024 fp32 in/out.
// All GEMMs: legacy mma.sync.m16n8k16 fp16 (fp32 accum) — 2x the tf32 rate.
// fp16 mantissa == tf32 mantissa (11 bits), values all in range -> same error.
// 4-stage cp.async pipeline, ldmatrix.x4, BM=BN=128, BK=32 halfs.
// ---------------------------------------------------------------------------

#define B_ 8
#define T_ 2048
#define F_ 1024

__device__ __half g_Xh [(size_t)B_ * T_ * F_];
__device__ __half g_Wqh[(size_t)F_ * F_];
__device__ __half g_Wkh[(size_t)F_ * F_];
__device__ __half g_Wvh[(size_t)F_ * F_];
__device__ __half g_Qh [(size_t)B_ * T_ * F_];
__device__ __half g_Kh [(size_t)B_ * T_ * F_];
__device__ __half g_Vh [(size_t)B_ * T_ * F_];
__device__ __half g_VTh[(size_t)B_ * T_ * F_];
__device__ __half g_Sh [(size_t)B_ * T_ * T_];

__device__ __forceinline__ void cpa16(uint32_t dst, const void* src) {
    asm volatile("cp.async.cg.shared.global [%0], [%1], 16;" :: "r"(dst), "l"(src));
}

#define MMA_F16(d, a, b)                                                      \
    asm volatile(                                                             \
        "mma.sync.aligned.m16n8k16.row.col.f32.f16.f16.f32 "                  \
        "{%0,%1,%2,%3},{%4,%5,%6,%7},{%8,%9},{%0,%1,%2,%3};"                  \
        : "+f"(d[0]), "+f"(d[1]), "+f"(d[2]), "+f"(d[3])                      \
        : "r"(a[0]), "r"(a[1]), "r"(a[2]), "r"(a[3]), "r"(b[0]), "r"(b[1]))

#define LDSM4(r0, r1, r2, r3, addr)                                           \
    asm volatile("ldmatrix.sync.aligned.m8n8.x4.shared.b16 {%0,%1,%2,%3},[%4];" \
        : "=r"(r0), "=r"(r1), "=r"(r2), "=r"(r3) : "r"(addr))

// ---------------------------------------------------------------------------
// smem tile geometry: 128 rows x 32 halfs, row stride 40 halfs (80 B).
// 80 B stride: 8 consecutive rows hit distinct bank groups; 16 B aligned.
// ---------------------------------------------------------------------------
#define LDH     40
#define STG_H   (128 * LDH)          // halfs per array per stage
#define STG_B   (STG_H * 2)          // 10240 bytes
#define NSTAGE  4
#define GEMM_SMEM (2 * NSTAGE * STG_B)   // 81920 bytes

// ---------------------------------------------------------------------------
// C[z] = alpha * A[z] @ B[z]^T (+ bias). A:[M,K] B:[N,K] row-major, fp16.
// Output fp16 (OUT_HALF) or fp32. 256 thr = 8 warps (2x4), warp tile 64x32.
// ---------------------------------------------------------------------------
template <bool HAS_BIAS, bool OUT_HALF>
__global__ __launch_bounds__(256, 2) void gemm_h(
    const __half* __restrict__ A, const __half* __restrict__ B,
    void* __restrict__ Cv, const float* __restrict__ bias,
    int N, int K,
    long long bsA, long long bsB, long long bsC, float alpha)
{
    extern __shared__ __half smem[];
    __half* sA = smem;
    __half* sB = smem + NSTAGE * STG_H;

    const int tid  = threadIdx.x;
    const int warp = tid >> 5, lane = tid & 31;
    const int wm   = warp >> 2;        // 0..1
    const int wn   = warp & 3;         // 0..3
    const int gid  = lane >> 2, tig = lane & 3;

    const int m0 = blockIdx.y * 128;
    const int n0 = blockIdx.x * 128;

    const __half* Ab = A + (size_t)blockIdx.z * bsA;
    const __half* Bb = B + (size_t)blockIdx.z * bsB;

    // cp.async: 512 16B-chunks per array per stage; 2 per thread per array
    const int cr0 = tid >> 2;          // rows 0..63   (chunk c = tid)
    const int cr1 = cr0 + 64;          // rows 64..127 (chunk c = tid+256)
    const int cc  = (tid & 3) * 8;     // half-col within 32-wide k-slab

    // ldmatrix lane addresses (stage-0 byte offsets)
    const uint32_t smem_b = (uint32_t)__cvta_generic_to_shared(smem);
    const int arow = wm * 64 + (lane & 15);
    const int acol = (lane >> 4) * 8;
    const uint32_t aBase = smem_b + (uint32_t)(arow * LDH + acol) * 2u;
    const int brow = wn * 32 + (lane & 7) + (lane >> 4) * 8;
    const int bcol = ((lane >> 3) & 1) * 8;
    const uint32_t bBase = smem_b + (uint32_t)(NSTAGE * STG_H) * 2u
                         + (uint32_t)(brow * LDH + bcol) * 2u;

    float acc[4][4][4];
#pragma unroll
    for (int i = 0; i < 4; i++)
#pragma unroll
        for (int j = 0; j < 4; j++)
#pragma unroll
            for (int c = 0; c < 4; c++) acc[i][j][c] = 0.0f;

    const int KT = K >> 5;

    auto issue = [&](int kt, int st) {
        const int kb = (kt << 5) + cc;
        __half* pA = sA + st * STG_H;
        __half* pB = sB + st * STG_H;
        cpa16((uint32_t)__cvta_generic_to_shared(pA + cr0 * LDH + cc),
              Ab + (size_t)(m0 + cr0) * K + kb);
        cpa16((uint32_t)__cvta_generic_to_shared(pA + cr1 * LDH + cc),
              Ab + (size_t)(m0 + cr1) * K + kb);
        cpa16((uint32_t)__cvta_generic_to_shared(pB + cr0 * LDH + cc),
              Bb + (size_t)(n0 + cr0) * K + kb);
        cpa16((uint32_t)__cvta_generic_to_shared(pB + cr1 * LDH + cc),
              Bb + (size_t)(n0 + cr1) * K + kb);
        asm volatile("cp.async.commit_group;");
    };

    issue(0, 0);
    issue(1, 1);
    issue(2, 2);

    for (int kt = 0; kt < KT; ++kt) {
        const int st = kt & (NSTAGE - 1);
        const int rem = KT - 1 - kt;
        if (rem >= 2)      asm volatile("cp.async.wait_group 2;");
        else if (rem == 1) asm volatile("cp.async.wait_group 1;");
        else               asm volatile("cp.async.wait_group 0;");
        __syncthreads();

        if (kt + 3 < KT) issue(kt + 3, (kt + 3) & (NSTAGE - 1));

        const uint32_t aSt = aBase + st * STG_B;
        const uint32_t bSt = bBase + st * STG_B;

#pragma unroll
        for (int ks = 0; ks < 2; ++ks) {
            const uint32_t ko = ks * 32;   // 16 halfs = 32 bytes
            uint32_t af[4][4], bf[4][2];
#pragma unroll
            for (int im = 0; im < 4; im++)
                LDSM4(af[im][0], af[im][1], af[im][2], af[im][3],
                      aSt + im * (16 * LDH * 2) + ko);
#pragma unroll
            for (int p = 0; p < 2; p++)
                LDSM4(bf[2 * p][0], bf[2 * p][1], bf[2 * p + 1][0], bf[2 * p + 1][1],
                      bSt + p * (16 * LDH * 2) + ko);
#pragma unroll
            for (int im = 0; im < 4; im++)
#pragma unroll
                for (int in_ = 0; in_ < 4; in_++)
                    MMA_F16(acc[im][in_], af[im], bf[in_]);
        }
        __syncthreads();
    }

    // Epilogue
#pragma unroll
    for (int im = 0; im < 4; im++) {
        const int r = m0 + wm * 64 + im * 16 + gid;
#pragma unroll
        for (int in_ = 0; in_ < 4; in_++) {
            const int col = n0 + wn * 32 + in_ * 8 + 2 * tig;
            float b0 = 0.0f, b1 = 0.0f;
            if (HAS_BIAS) { b0 = bias[col]; b1 = bias[col + 1]; }
            float o00 = alpha * acc[im][in_][0] + b0;
            float o01 = alpha * acc[im][in_][1] + b1;
            float o10 = alpha * acc[im][in_][2] + b0;
            float o11 = alpha * acc[im][in_][3] + b1;
            if (OUT_HALF) {
                __half* Cb = (__half*)Cv + (size_t)blockIdx.z * bsC;
                *(__half2*)(Cb + (size_t)r * N + col)       = __floats2half2_rn(o00, o01);
                *(__half2*)(Cb + (size_t)(r + 8) * N + col) = __floats2half2_rn(o10, o11);
            } else {
                float* Cb = (float*)Cv + (size_t)blockIdx.z * bsC;
                *(float2*)(Cb + (size_t)r * N + col)       = make_float2(o00, o01);
                *(float2*)(Cb + (size_t)(r + 8) * N + col) = make_float2(o10, o11);
            }
        }
    }
}

// ---------------------------------------------------------------------------
// fp32 -> fp16 conversion (vectorized: 4 floats -> 2 half2 per thread)
// ---------------------------------------------------------------------------
__global__ void cvt_pass(const float4* __restrict__ in, __half2* __restrict__ out)
{
    const int i = blockIdx.x * blockDim.x + threadIdx.x;
    float4 v = in[i];
    out[2 * i]     = __floats2half2_rn(v.x, v.y);
    out[2 * i + 1] = __floats2half2_rn(v.z, v.w);
}

// ---------------------------------------------------------------------------
// Batched half transpose: V [B][T][F] -> VT [B][F][T]
// ---------------------------------------------------------------------------
__global__ void transpose_h(const __half* __restrict__ in, __half* __restrict__ out)
{
    __shared__ __half t[32][33];
    const int z  = blockIdx.z;
    const int s0 = blockIdx.x * 32;
    const int f0 = blockIdx.y * 32;
    const __half* ib = in  + (size_t)z * T_ * F_;
    __half*       ob = out + (size_t)z * T_ * F_;
    const int tx = threadIdx.x, ty = threadIdx.y;
#pragma unroll
    for (int i = 0; i < 32; i += 8)
        t[ty + i][tx] = ib[(size_t)(s0 + ty + i) * F_ + f0 + tx];
    __syncthreads();
#pragma unroll
    for (int i = 0; i < 32; i += 8)
        ob[(size_t)(f0 + ty + i) * T_ + s0 + tx] = t[tx][ty + i];
}

// ---------------------------------------------------------------------------
// Row softmax over 2048 half values per row; fp32 math; in-place half output.
// grid (T_, B_), block 256. Each thread: 4 half2 (8 values).
// ---------------------------------------------------------------------------
__global__ __launch_bounds__(256) void softmax2048h(__half2* __restrict__ S)
{
    __half2* p = S + ((size_t)blockIdx.y * T_ + blockIdx.x) * (T_ / 2);
    const int tid = threadIdx.x;
    __shared__ float rmax[8], rsum[8];

    float2 v[4];
    float m = -3.0e38f;
#pragma unroll
    for (int i = 0; i < 4; i++) {
        v[i] = __half22float2(p[tid + (i << 8)]);
        m = fmaxf(m, fmaxf(v[i].x, v[i].y));
    }
#pragma unroll
    for (int o = 16; o > 0; o >>= 1) m = fmaxf(m, __shfl_xor_sync(0xffffffffu, m, o));
    if ((tid & 31) == 0) rmax[tid >> 5] = m;
    __syncthreads();
    float bm = rmax[0];
#pragma unroll
    for (int i = 1; i < 8; i++) bm = fmaxf(bm, rmax[i]);

    float s = 0.0f;
#pragma unroll
    for (int i = 0; i < 4; i++) {
        v[i].x = __expf(v[i].x - bm); v[i].y = __expf(v[i].y - bm);
        s += v[i].x + v[i].y;
    }
#pragma unroll
    for (int o = 16; o > 0; o >>= 1) s += __shfl_xor_sync(0xffffffffu, s, o);
    if ((tid & 31) == 0) rsum[tid >> 5] = s;
    __syncthreads();
    float bs = 0.0f;
#pragma unroll
    for (int i = 0; i < 8; i++) bs += rsum[i];

    const float inv = 1.0f / bs;
#pragma unroll
    for (int i = 0; i < 4; i++)
        p[tid + (i << 8)] = __floats2half2_rn(v[i].x * inv, v[i].y * inv);
}

// ---------------------------------------------------------------------------
extern "C" void kernel_launch(void* const* d_in, const int* in_sizes, int n_in,
                              void* d_out, int out_size)
{
    const float* X  = (const float*)d_in[0];
    const float* Wq = (const float*)d_in[1];
    const float* bq = (const float*)d_in[2];
    const float* Wk = (const float*)d_in[3];
    const float* bk = (const float*)d_in[4];
    const float* Wv = (const float*)d_in[5];
    const float* bv = (const float*)d_in[6];
    float* O = (float*)d_out;

    __half *Xh, *Wqh, *Wkh, *Wvh, *Qh, *Kh, *Vh, *VTh, *Sh;
    cudaGetSymbolAddress((void**)&Xh,  g_Xh);
    cudaGetSymbolAddress((void**)&Wqh, g_Wqh);
    cudaGetSymbolAddress((void**)&Wkh, g_Wkh);
    cudaGetSymbolAddress((void**)&Wvh, g_Wvh);
    cudaGetSymbolAddress((void**)&Qh,  g_Qh);
    cudaGetSymbolAddress((void**)&Kh,  g_Kh);
    cudaGetSymbolAddress((void**)&Vh,  g_Vh);
    cudaGetSymbolAddress((void**)&VTh, g_VTh);
    cudaGetSymbolAddress((void**)&Sh,  g_Sh);

    cudaFuncSetAttribute(gemm_h<true, true>,
                         cudaFuncAttributeMaxDynamicSharedMemorySize, GEMM_SMEM);
    cudaFuncSetAttribute(gemm_h<false, true>,
                         cudaFuncAttributeMaxDynamicSharedMemorySize, GEMM_SMEM);
    cudaFuncSetAttribute(gemm_h<false, false>,
                         cudaFuncAttributeMaxDynamicSharedMemorySize, GEMM_SMEM);

    const dim3 blk(256);

    // fp32 -> fp16 inputs
    cvt_pass<<<(B_ * T_ * F_ / 4) / 256, 256>>>((const float4*)X,  (__half2*)Xh);
    cvt_pass<<<(F_ * F_ / 4) / 256,     256>>>((const float4*)Wq, (__half2*)Wqh);
    cvt_pass<<<(F_ * F_ / 4) / 256,     256>>>((const float4*)Wk, (__half2*)Wkh);
    cvt_pass<<<(F_ * F_ / 4) / 256,     256>>>((const float4*)Wv, (__half2*)Wvh);

    // QKV projections: [16384,1024] = Xh @ W^T + b  (half out)
    gemm_h<true, true><<<dim3(8, 128, 1), blk, GEMM_SMEM>>>(
        Xh, Wqh, Qh, bq, F_, F_, 0, 0, 0, 1.0f);
    gemm_h<true, true><<<dim3(8, 128, 1), blk, GEMM_SMEM>>>(
        Xh, Wkh, Kh, bk, F_, F_, 0, 0, 0, 1.0f);
    gemm_h<true, true><<<dim3(8, 128, 1), blk, GEMM_SMEM>>>(
        Xh, Wvh, Vh, bv, F_, F_, 0, 0, 0, 1.0f);

    transpose_h<<<dim3(T_ / 32, F_ / 32, B_), dim3(32, 8)>>>(Vh, VTh);

    // scores: S[z] = (Q K^T) / 32 (half out)
    gemm_h<false, true><<<dim3(16, 16, B_), blk, GEMM_SMEM>>>(
        Qh, Kh, Sh, nullptr, T_, F_,
        (long long)T_ * F_, (long long)T_ * F_, (long long)T_ * T_, 0.03125f);

    softmax2048h<<<dim3(T_, B_), blk>>>((__half2*)Sh);

    // O[z] = S V = S @ VT^T (fp32 out)
    gemm_h<false, false><<<dim3(8, 16, B_), blk, GEMM_SMEM>>>(
        Sh, VTh, O, nullptr, F_, T_,
        (long long)T_ * T_, (long long)F_ * T_, (long long)T_ * F_, 1.0f);
}

// round 5
// speedup vs baseline: 2.0456x; 1.0082x over previous
#include <cuda_runtime.h>
#include <cuda_fp16.h>
#include <cstdint>
#include <cstddef>

// ---------------------------------------------------------------------------
// Self-attention B=8,T=2048,D=1024 fp32 in/out.
// fp16 m16n8k16 mma (fp32 accum) at the legacy-HMMA ceiling; this round:
// persistent GEMMs w/ dynamic tile stealing, fused QK-proj + direct-VT launch.
// ---------------------------------------------------------------------------

#define B_ 8
#define T_ 2048
#define F_ 1024

__device__ __half g_Xh  [(size_t)B_ * T_ * F_];
__device__ __half g_Wcat[(size_t)3 * F_ * F_];      // [Wq ; Wk ; Wv]
__device__ float  g_bcat[2 * F_];                   // [bq ; bk]
__device__ __half g_QKh [(size_t)B_ * T_ * 2 * F_]; // [B*T][Q(1024)|K(1024)]
__device__ __half g_VTh [(size_t)B_ * F_ * T_];     // [B][F][T]
__device__ __half g_Sh  [(size_t)B_ * T_ * T_];
__device__ unsigned g_ctrs[4];

__device__ __forceinline__ void cpa16(uint32_t dst, const void* src) {
    asm volatile("cp.async.cg.shared.global [%0], [%1], 16;" :: "r"(dst), "l"(src));
}

#define MMA_F16(d, a, b)                                                      \
    asm volatile(                                                             \
        "mma.sync.aligned.m16n8k16.row.col.f32.f16.f16.f32 "                  \
        "{%0,%1,%2,%3},{%4,%5,%6,%7},{%8,%9},{%0,%1,%2,%3};"                  \
        : "+f"(d[0]), "+f"(d[1]), "+f"(d[2]), "+f"(d[3])                      \
        : "r"(a[0]), "r"(a[1]), "r"(a[2]), "r"(a[3]), "r"(b[0]), "r"(b[1]))

#define LDSM4(r0, r1, r2, r3, addr)                                           \
    asm volatile("ldmatrix.sync.aligned.m8n8.x4.shared.b16 {%0,%1,%2,%3},[%4];" \
        : "=r"(r0), "=r"(r1), "=r"(r2), "=r"(r3) : "r"(addr))

#define LDH     40                   // smem row stride in halfs (80 B)
#define STG_H   (128 * LDH)
#define STG_B   (STG_H * 2)
#define NSTAGE  4
#define GEMM_SMEM (2 * NSTAGE * STG_B)   // 81920 bytes

// bias/out mode bits: 1=col bias, 2=row bias, 4=half output
struct Job {
    const __half* A; const __half* B; void* C; const float* bias;
    int N, K, lda, ldb, ldc;
    long long bsA, bsB, bsC;
    float alpha;
    int nx, ny, ntiles, mode;
};

// ---------------------------------------------------------------------------
// One 128x128 output tile of C = alpha * A@B^T (+bias), fp16 in, fp32 acc.
// ---------------------------------------------------------------------------
__device__ __forceinline__ void gemm_tile(const Job* __restrict__ J,
                                          int tx, int ty, int tz,
                                          __half* smem, int tid)
{
    __half* sA = smem;
    __half* sB = smem + NSTAGE * STG_H;

    const int warp = tid >> 5, lane = tid & 31;
    const int wm = warp >> 2, wn = warp & 3;
    const int gid = lane >> 2, tig = lane & 3;

    const int m0 = ty * 128, n0 = tx * 128;
    const int lda = J->lda, ldb = J->ldb;
    const __half* Ab = J->A + (size_t)tz * J->bsA;
    const __half* Bb = J->B + (size_t)tz * J->bsB;

    const int cr0 = tid >> 2, cr1 = cr0 + 64;
    const int ccc = (tid & 3) * 8;

    const uint32_t smem_b = (uint32_t)__cvta_generic_to_shared(smem);
    const int arow = wm * 64 + (lane & 15);
    const int acol = (lane >> 4) * 8;
    const uint32_t aBase = smem_b + (uint32_t)(arow * LDH + acol) * 2u;
    const int brow = wn * 32 + (lane & 7) + (lane >> 4) * 8;
    const int bcol = ((lane >> 3) & 1) * 8;
    const uint32_t bBase = smem_b + (uint32_t)(NSTAGE * STG_H) * 2u
                         + (uint32_t)(brow * LDH + bcol) * 2u;

    float acc[4][4][4];
#pragma unroll
    for (int i = 0; i < 4; i++)
#pragma unroll
        for (int j = 0; j < 4; j++)
#pragma unroll
            for (int c = 0; c < 4; c++) acc[i][j][c] = 0.0f;

    const int KT = J->K >> 5;

    auto issue = [&](int kt, int st) {
        const int kb = (kt << 5) + ccc;
        __half* pA = sA + st * STG_H;
        __half* pB = sB + st * STG_H;
        cpa16((uint32_t)__cvta_generic_to_shared(pA + cr0 * LDH + ccc),
              Ab + (size_t)(m0 + cr0) * lda + kb);
        cpa16((uint32_t)__cvta_generic_to_shared(pA + cr1 * LDH + ccc),
              Ab + (size_t)(m0 + cr1) * lda + kb);
        cpa16((uint32_t)__cvta_generic_to_shared(pB + cr0 * LDH + ccc),
              Bb + (size_t)(n0 + cr0) * ldb + kb);
        cpa16((uint32_t)__cvta_generic_to_shared(pB + cr1 * LDH + ccc),
              Bb + (size_t)(n0 + cr1) * ldb + kb);
        asm volatile("cp.async.commit_group;");
    };

    issue(0, 0);
    issue(1, 1);
    issue(2, 2);

#pragma unroll 1
    for (int kt = 0; kt < KT; ++kt) {
        const int st = kt & (NSTAGE - 1);
        const int rem = KT - 1 - kt;
        if (rem >= 2)      asm volatile("cp.async.wait_group 2;");
        else if (rem == 1) asm volatile("cp.async.wait_group 1;");
        else               asm volatile("cp.async.wait_group 0;");
        __syncthreads();

        if (kt + 3 < KT) issue(kt + 3, (kt + 3) & (NSTAGE - 1));

        const uint32_t aSt = aBase + st * STG_B;
        const uint32_t bSt = bBase + st * STG_B;

#pragma unroll
        for (int ks = 0; ks < 2; ++ks) {
            const uint32_t ko = ks * 32;
            uint32_t af[4][4], bf[4][2];
#pragma unroll
            for (int im = 0; im < 4; im++)
                LDSM4(af[im][0], af[im][1], af[im][2], af[im][3],
                      aSt + im * (16 * LDH * 2) + ko);
#pragma unroll
            for (int p = 0; p < 2; p++)
                LDSM4(bf[2 * p][0], bf[2 * p][1], bf[2 * p + 1][0], bf[2 * p + 1][1],
                      bSt + p * (16 * LDH * 2) + ko);
#pragma unroll
            for (int im = 0; im < 4; im++)
#pragma unroll
                for (int in_ = 0; in_ < 4; in_++)
                    MMA_F16(acc[im][in_], af[im], bf[in_]);
        }
        __syncthreads();
    }

    // ---- epilogue ----
    const int   bm    = J->mode & 3;
    const bool  ohalf = (J->mode & 4) != 0;
    const float alpha = J->alpha;
    const float* bias = J->bias;
    const int   ldc   = J->ldc;

#pragma unroll
    for (int im = 0; im < 4; im++) {
        const int r = m0 + wm * 64 + im * 16 + gid;
        float br0 = 0.f, br8 = 0.f;
        if (bm == 2) { br0 = bias[r]; br8 = bias[r + 8]; }
#pragma unroll
        for (int in_ = 0; in_ < 4; in_++) {
            const int col = n0 + wn * 32 + in_ * 8 + 2 * tig;
            float o00 = alpha * acc[im][in_][0];
            float o01 = alpha * acc[im][in_][1];
            float o10 = alpha * acc[im][in_][2];
            float o11 = alpha * acc[im][in_][3];
            if (bm == 1) {
                const float c0 = bias[col], c1 = bias[col + 1];
                o00 += c0; o01 += c1; o10 += c0; o11 += c1;
            } else if (bm == 2) {
                o00 += br0; o01 += br0; o10 += br8; o11 += br8;
            }
            if (ohalf) {
                __half* Cb = (__half*)J->C + (size_t)tz * J->bsC;
                *(__half2*)(Cb + (size_t)r * ldc + col)       = __floats2half2_rn(o00, o01);
                *(__half2*)(Cb + (size_t)(r + 8) * ldc + col) = __floats2half2_rn(o10, o11);
            } else {
                float* Cb = (float*)J->C + (size_t)tz * J->bsC;
                *(float2*)(Cb + (size_t)r * ldc + col)       = make_float2(o00, o01);
                *(float2*)(Cb + (size_t)(r + 8) * ldc + col) = make_float2(o10, o11);
            }
        }
    }
}

// ---------------------------------------------------------------------------
// Persistent driver: dynamic tile stealing over up to two jobs' tile pools.
// ---------------------------------------------------------------------------
__global__ __launch_bounds__(256, 2) void gemm_persist(Job j0, Job j1,
                                                       int njobs, int ctr_idx)
{
    extern __shared__ __half smem[];
    __shared__ unsigned s_t;
    const int tid = threadIdx.x;
    const unsigned total = (unsigned)(j0.ntiles + (njobs > 1 ? j1.ntiles : 0));

#pragma unroll 1
    while (true) {
        if (tid == 0) s_t = atomicAdd(&g_ctrs[ctr_idx], 1u);
        __syncthreads();
        unsigned t = s_t;
        if (t >= total) return;

        const Job* J = &j0;
        if (t >= (unsigned)j0.ntiles) { J = &j1; t -= (unsigned)j0.ntiles; }
        const unsigned per = (unsigned)(J->nx * J->ny);
        const int tz = (int)(t / per);
        const unsigned rr = t - (unsigned)tz * per;
        const int ty = (int)(rr / (unsigned)J->nx);
        const int tx = (int)(rr - (unsigned)ty * (unsigned)J->nx);

        gemm_tile(J, tx, ty, tz, smem, tid);
        __syncthreads();   // all done with s_t + smem before next grab
    }
}

// ---------------------------------------------------------------------------
// fp32 -> fp16 converters
// ---------------------------------------------------------------------------
__global__ void cvt_x(const float4* __restrict__ in, __half2* __restrict__ out)
{
    const int i = (blockIdx.x * blockDim.x + threadIdx.x) * 2;
    float4 a = in[i], b = in[i + 1];
    out[2 * i]     = __floats2half2_rn(a.x, a.y);
    out[2 * i + 1] = __floats2half2_rn(a.z, a.w);
    out[2 * i + 2] = __floats2half2_rn(b.x, b.y);
    out[2 * i + 3] = __floats2half2_rn(b.z, b.w);
}

__global__ void cvt_w3(const float4* __restrict__ w0, const float4* __restrict__ w1,
                       const float4* __restrict__ w2, __half2* __restrict__ out)
{
    const float4* src = (blockIdx.y == 0) ? w0 : ((blockIdx.y == 1) ? w1 : w2);
    __half2* dst = out + (size_t)blockIdx.y * (F_ * F_ / 2);
    const int i = blockIdx.x * blockDim.x + threadIdx.x;
    float4 v = src[i];
    dst[2 * i]     = __floats2half2_rn(v.x, v.y);
    dst[2 * i + 1] = __floats2half2_rn(v.z, v.w);
}

// ---------------------------------------------------------------------------
// Row softmax over 2048 halfs; fp32 math; in-place.
// ---------------------------------------------------------------------------
__global__ __launch_bounds__(256) void softmax2048h(__half2* __restrict__ S)
{
    __half2* p = S + ((size_t)blockIdx.y * T_ + blockIdx.x) * (T_ / 2);
    const int tid = threadIdx.x;
    __shared__ float rmax[8], rsum[8];

    float2 v[4];
    float m = -3.0e38f;
#pragma unroll
    for (int i = 0; i < 4; i++) {
        v[i] = __half22float2(p[tid + (i << 8)]);
        m = fmaxf(m, fmaxf(v[i].x, v[i].y));
    }
#pragma unroll
    for (int o = 16; o > 0; o >>= 1) m = fmaxf(m, __shfl_xor_sync(0xffffffffu, m, o));
    if ((tid & 31) == 0) rmax[tid >> 5] = m;
    __syncthreads();
    float bm = rmax[0];
#pragma unroll
    for (int i = 1; i < 8; i++) bm = fmaxf(bm, rmax[i]);

    float s = 0.0f;
#pragma unroll
    for (int i = 0; i < 4; i++) {
        v[i].x = __expf(v[i].x - bm); v[i].y = __expf(v[i].y - bm);
        s += v[i].x + v[i].y;
    }
#pragma unroll
    for (int o = 16; o > 0; o >>= 1) s += __shfl_xor_sync(0xffffffffu, s, o);
    if ((tid & 31) == 0) rsum[tid >> 5] = s;
    __syncthreads();
    float bs = 0.0f;
#pragma unroll
    for (int i = 0; i < 8; i++) bs += rsum[i];

    const float inv = 1.0f / bs;
#pragma unroll
    for (int i = 0; i < 4; i++)
        p[tid + (i << 8)] = __floats2half2_rn(v[i].x * inv, v[i].y * inv);
}

// ---------------------------------------------------------------------------
extern "C" void kernel_launch(void* const* d_in, const int* in_sizes, int n_in,
                              void* d_out, int out_size)
{
    const float* X  = (const float*)d_in[0];
    const float* Wq = (const float*)d_in[1];
    const float* bq = (const float*)d_in[2];
    const float* Wk = (const float*)d_in[3];
    const float* bk = (const float*)d_in[4];
    const float* Wv = (const float*)d_in[5];
    const float* bv = (const float*)d_in[6];
    float* O = (float*)d_out;

    __half *Xh, *Wcat, *QKh, *VTh, *Sh;
    float* bcat;
    unsigned* ctrs;
    cudaGetSymbolAddress((void**)&Xh,   g_Xh);
    cudaGetSymbolAddress((void**)&Wcat, g_Wcat);
    cudaGetSymbolAddress((void**)&bcat, g_bcat);
    cudaGetSymbolAddress((void**)&QKh,  g_QKh);
    cudaGetSymbolAddress((void**)&VTh,  g_VTh);
    cudaGetSymbolAddress((void**)&Sh,   g_Sh);
    cudaGetSymbolAddress((void**)&ctrs, g_ctrs);

    cudaFuncSetAttribute(gemm_persist,
                         cudaFuncAttributeMaxDynamicSharedMemorySize, GEMM_SMEM);

    int sms = 148;
    cudaDeviceGetAttribute(&sms, cudaDevAttrMultiProcessorCount, 0);
    const int PGRID = 2 * sms;

    // reset tile counters (re-executed on every graph replay)
    cudaMemsetAsync(ctrs, 0, 4 * sizeof(unsigned));

    // convert inputs to fp16
    cvt_x<<<B_ * T_ * F_ / (256 * 8), 256>>>((const float4*)X, (__half2*)Xh);
    cvt_w3<<<dim3(F_ * F_ / (256 * 4), 3), 256>>>(
        (const float4*)Wq, (const float4*)Wk, (const float4*)Wv, (__half2*)Wcat);
    cudaMemcpyAsync(bcat,      bq, F_ * sizeof(float), cudaMemcpyDeviceToDevice);
    cudaMemcpyAsync(bcat + F_, bk, F_ * sizeof(float), cudaMemcpyDeviceToDevice);

    // ---- launch A: fused QK projection + direct-VT projection ----
    Job jQK = {};
    jQK.A = Xh;  jQK.B = Wcat; jQK.C = QKh; jQK.bias = bcat;
    jQK.N = 2 * F_; jQK.K = F_; jQK.lda = F_; jQK.ldb = F_; jQK.ldc = 2 * F_;
    jQK.bsA = 0; jQK.bsB = 0; jQK.bsC = 0;
    jQK.alpha = 1.0f; jQK.nx = 16; jQK.ny = 128; jQK.ntiles = 2048;
    jQK.mode = 1 | 4;   // col bias, half out

    Job jVT = {};
    jVT.A = Wcat + (size_t)2 * F_ * F_;  jVT.B = Xh;  jVT.C = VTh;  jVT.bias = bv;
    jVT.N = T_; jVT.K = F_; jVT.lda = F_; jVT.ldb = F_; jVT.ldc = T_;
    jVT.bsA = 0; jVT.bsB = (long long)T_ * F_; jVT.bsC = (long long)F_ * T_;
    jVT.alpha = 1.0f; jVT.nx = 16; jVT.ny = 8; jVT.ntiles = 8 * 16 * 8;
    jVT.mode = 2 | 4;   // row bias, half out

    gemm_persist<<<PGRID, 256, GEMM_SMEM>>>(jQK, jVT, 2, 0);

    // ---- launch B: scores S = (Q K^T)/32 ----
    Job jS = {};
    jS.A = QKh;  jS.B = QKh + F_;  jS.C = Sh;  jS.bias = nullptr;
    jS.N = T_; jS.K = F_; jS.lda = 2 * F_; jS.ldb = 2 * F_; jS.ldc = T_;
    jS.bsA = (long long)T_ * 2 * F_; jS.bsB = (long long)T_ * 2 * F_;
    jS.bsC = (long long)T_ * T_;
    jS.alpha = 0.03125f; jS.nx = 16; jS.ny = 16; jS.ntiles = 8 * 16 * 16;
    jS.mode = 4;        // half out

    gemm_persist<<<PGRID, 256, GEMM_SMEM>>>(jS, jS, 1, 1);

    softmax2048h<<<dim3(T_, B_), 256>>>((__half2*)Sh);

    // ---- launch C: O = P V = P @ VT^T (fp32 out) ----
    Job jO = {};
    jO.A = Sh;  jO.B = VTh;  jO.C = O;  jO.bias = nullptr;
    jO.N = F_; jO.K = T_; jO.lda = T_; jO.ldb = T_; jO.ldc = F_;
    jO.bsA = (long long)T_ * T_; jO.bsB = (long long)F_ * T_;
    jO.bsC = (long long)T_ * F_;
    jO.alpha = 1.0f; jO.nx = 8; jO.ny = 16; jO.ntiles = 8 * 16 * 8;
    jO.mode = 0;        // fp32 out, no bias

    gemm_persist<<<PGRID, 256, GEMM_SMEM>>>(jO, jO, 1, 2);
}

// round 10
// speedup vs baseline: 2.1675x; 1.0596x over previous
#include <cuda_runtime.h>
#include <cuda_fp16.h>
#include <cstdint>
#include <cstddef>

// ---------------------------------------------------------------------------
// Self-attention B=8,T=2048,D=1024 fp32 in/out.
// fp16 m16n8k16 mma (fp32 accum). Persistent GEMMs, dynamic tile stealing.
// This round: BK=64, NSTAGE=3, ONE __syncthreads per k64 ktile, BM=64 path
// for the O-GEMM (tail reduction).
// ---------------------------------------------------------------------------

#define B_ 8
#define T_ 2048
#define F_ 1024

__device__ __half g_Xh  [(size_t)B_ * T_ * F_];
__device__ __half g_Wcat[(size_t)3 * F_ * F_];      // [Wq ; Wk ; Wv]
__device__ float  g_bcat[2 * F_];                   // [bq ; bk]
__device__ __half g_QKh [(size_t)B_ * T_ * 2 * F_]; // [B*T][Q|K]
__device__ __half g_VTh [(size_t)B_ * F_ * T_];     // [B][F][T]
__device__ __half g_Sh  [(size_t)B_ * T_ * T_];
__device__ unsigned g_ctrs[4];

__device__ __forceinline__ void cpa16(uint32_t dst, const void* src) {
    asm volatile("cp.async.cg.shared.global [%0], [%1], 16;" :: "r"(dst), "l"(src));
}

#define MMA_F16(d, a, b)                                                      \
    asm volatile(                                                             \
        "mma.sync.aligned.m16n8k16.row.col.f32.f16.f16.f32 "                  \
        "{%0,%1,%2,%3},{%4,%5,%6,%7},{%8,%9},{%0,%1,%2,%3};"                  \
        : "+f"(d[0]), "+f"(d[1]), "+f"(d[2]), "+f"(d[3])                      \
        : "r"(a[0]), "r"(a[1]), "r"(a[2]), "r"(a[3]), "r"(b[0]), "r"(b[1]))

#define LDSM4(r0, r1, r2, r3, addr)                                           \
    asm volatile("ldmatrix.sync.aligned.m8n8.x4.shared.b16 {%0,%1,%2,%3},[%4];" \
        : "=r"(r0), "=r"(r1), "=r"(r2), "=r"(r3) : "r"(addr))

// ---------------------------------------------------------------------------
// smem: 128 rows x 64 halfs per array per stage, row stride 72 halfs (144 B).
// 144 mod 128 = 16 -> 8 consecutive rows' 16B chunks tile all banks exactly.
// ---------------------------------------------------------------------------
#define LDH     72
#define ROWB    144                  // bytes per row
#define STG_H   (128 * LDH)
#define STG_B   (STG_H * 2)          // 18432 bytes
#define NSTAGE  3
#define GEMM_SMEM (2 * NSTAGE * STG_B)   // 110592 bytes

// mode bits: 1=col bias, 2=row bias, 4=half output, 8=BM64 tile
struct Job {
    const __half* A; const __half* B; void* C; const float* bias;
    int N, K, lda, ldb, ldc;
    long long bsA, bsB, bsC;
    float alpha;
    int nx, ny, ntiles, mode;
};

// ---------------------------------------------------------------------------
// Shared epilogue store helper
// ---------------------------------------------------------------------------
__device__ __forceinline__ void epi_store(const Job* J, int tz, int r, int col,
                                          float o00, float o01, float o10, float o11)
{
    const int bm = J->mode & 3;
    if (bm == 1) {
        const float c0 = J->bias[col], c1 = J->bias[col + 1];
        o00 += c0; o01 += c1; o10 += c0; o11 += c1;
    } else if (bm == 2) {
        const float r0 = J->bias[r], r8 = J->bias[r + 8];
        o00 += r0; o01 += r0; o10 += r8; o11 += r8;
    }
    const int ldc = J->ldc;
    if (J->mode & 4) {
        __half* Cb = (__half*)J->C + (size_t)tz * J->bsC;
        *(__half2*)(Cb + (size_t)r * ldc + col)       = __floats2half2_rn(o00, o01);
        *(__half2*)(Cb + (size_t)(r + 8) * ldc + col) = __floats2half2_rn(o10, o11);
    } else {
        float* Cb = (float*)J->C + (size_t)tz * J->bsC;
        *(float2*)(Cb + (size_t)r * ldc + col)       = make_float2(o00, o01);
        *(float2*)(Cb + (size_t)(r + 8) * ldc + col) = make_float2(o10, o11);
    }
}

// ---------------------------------------------------------------------------
// 128x128 tile: 8 warps (2x4), warp tile 64x32, BK=64, 3 stages, 1 sync/ktile
// ---------------------------------------------------------------------------
__device__ __forceinline__ void tile128(const Job* __restrict__ J,
                                        int tx, int ty, int tz,
                                        __half* smem, int tid)
{
    const int warp = tid >> 5, lane = tid & 31;
    const int wm = warp >> 2, wn = warp & 3;
    const int gid = lane >> 2, tig = lane & 3;

    const int m0 = ty * 128, n0 = tx * 128;
    const int lda = J->lda, ldb = J->ldb;
    const __half* Ab = J->A + (size_t)tz * J->bsA;
    const __half* Bb = J->B + (size_t)tz * J->bsB;

    // cp.async coords: row group (tid>>3) 0..31, chunk (tid&7)*8 halfs
    const int prow = tid >> 3;
    const int pch  = (tid & 7) * 8;

    const uint32_t smem_b = (uint32_t)__cvta_generic_to_shared(smem);
    const uint32_t aBase = smem_b
        + (uint32_t)(wm * 64 + (lane & 15)) * ROWB + (uint32_t)(lane >> 4) * 16u;
    const uint32_t bBase = smem_b + (uint32_t)(NSTAGE * STG_B)
        + (uint32_t)(wn * 32 + (lane & 7) + (lane >> 4) * 8) * ROWB
        + (uint32_t)((lane >> 3) & 1) * 16u;

    float acc[4][4][4];
#pragma unroll
    for (int i = 0; i < 4; i++)
#pragma unroll
        for (int j = 0; j < 4; j++)
#pragma unroll
            for (int c = 0; c < 4; c++) acc[i][j][c] = 0.0f;

    const int KT = J->K >> 6;

    auto issue = [&](int kt, int st) {
        const int kb = (kt << 6) + pch;
        const uint32_t aS = smem_b + st * STG_B + prow * ROWB + (pch << 1);
        const uint32_t bS = aS + (uint32_t)(NSTAGE * STG_B);
#pragma unroll
        for (int r = 0; r < 4; r++) {
            cpa16(aS + r * (32 * ROWB), Ab + (size_t)(m0 + prow + r * 32) * lda + kb);
            cpa16(bS + r * (32 * ROWB), Bb + (size_t)(n0 + prow + r * 32) * ldb + kb);
        }
        asm volatile("cp.async.commit_group;");
    };

    issue(0, 0);
    issue(1, 1);

    int st = 0;
#pragma unroll 1
    for (int kt = 0; kt < KT; ++kt) {
        if (kt < KT - 1) asm volatile("cp.async.wait_group 1;");
        else             asm volatile("cp.async.wait_group 0;");
        __syncthreads();

        if (kt + 2 < KT) {
            int stw = st + 2; if (stw >= NSTAGE) stw -= NSTAGE;
            issue(kt + 2, stw);
        }

        const uint32_t aSt = aBase + st * STG_B;
        const uint32_t bSt = bBase + st * STG_B;

#pragma unroll
        for (int ks = 0; ks < 4; ++ks) {
            const uint32_t ko = ks * 32;   // 16 halfs
            uint32_t af[4][4], bf[4][2];
#pragma unroll
            for (int im = 0; im < 4; im++)
                LDSM4(af[im][0], af[im][1], af[im][2], af[im][3],
                      aSt + im * (16 * ROWB) + ko);
#pragma unroll
            for (int p = 0; p < 2; p++)
                LDSM4(bf[2 * p][0], bf[2 * p][1], bf[2 * p + 1][0], bf[2 * p + 1][1],
                      bSt + p * (16 * ROWB) + ko);
#pragma unroll
            for (int im = 0; im < 4; im++)
#pragma unroll
                for (int in_ = 0; in_ < 4; in_++)
                    MMA_F16(acc[im][in_], af[im], bf[in_]);
        }
        if (++st >= NSTAGE) st = 0;
    }
    __syncthreads();   // protect smem before next tile's issue

    const float alpha = J->alpha;
#pragma unroll
    for (int im = 0; im < 4; im++) {
        const int r = m0 + wm * 64 + im * 16 + gid;
#pragma unroll
        for (int in_ = 0; in_ < 4; in_++) {
            const int col = n0 + wn * 32 + in_ * 8 + 2 * tig;
            epi_store(J, tz, r, col,
                      alpha * acc[im][in_][0], alpha * acc[im][in_][1],
                      alpha * acc[im][in_][2], alpha * acc[im][in_][3]);
        }
    }
}

// ---------------------------------------------------------------------------
// 64x128 tile: 8 warps (2x4), warp tile 32x32 (for tail-sensitive O-GEMM)
// ---------------------------------------------------------------------------
__device__ __forceinline__ void tile64(const Job* __restrict__ J,
                                       int tx, int ty, int tz,
                                       __half* smem, int tid)
{
    const int warp = tid >> 5, lane = tid & 31;
    const int wm = warp >> 2, wn = warp & 3;   // wm 0..1 -> 32 rows each
    const int gid = lane >> 2, tig = lane & 3;

    const int m0 = ty * 64, n0 = tx * 128;
    const int lda = J->lda, ldb = J->ldb;
    const __half* Ab = J->A + (size_t)tz * J->bsA;
    const __half* Bb = J->B + (size_t)tz * J->bsB;

    const int prow = tid >> 3;
    const int pch  = (tid & 7) * 8;

    const uint32_t smem_b = (uint32_t)__cvta_generic_to_shared(smem);
    const uint32_t aBase = smem_b
        + (uint32_t)(wm * 32 + (lane & 15)) * ROWB + (uint32_t)(lane >> 4) * 16u;
    const uint32_t bBase = smem_b + (uint32_t)(NSTAGE * STG_B)
        + (uint32_t)(wn * 32 + (lane & 7) + (lane >> 4) * 8) * ROWB
        + (uint32_t)((lane >> 3) & 1) * 16u;

    float acc[2][4][4];
#pragma unroll
    for (int i = 0; i < 2; i++)
#pragma unroll
        for (int j = 0; j < 4; j++)
#pragma unroll
            for (int c = 0; c < 4; c++) acc[i][j][c] = 0.0f;

    const int KT = J->K >> 6;

    auto issue = [&](int kt, int st) {
        const int kb = (kt << 6) + pch;
        const uint32_t aS = smem_b + st * STG_B + prow * ROWB + (pch << 1);
        const uint32_t bS = aS + (uint32_t)(NSTAGE * STG_B);
#pragma unroll
        for (int r = 0; r < 2; r++)
            cpa16(aS + r * (32 * ROWB), Ab + (size_t)(m0 + prow + r * 32) * lda + kb);
#pragma unroll
        for (int r = 0; r < 4; r++)
            cpa16(bS + r * (32 * ROWB), Bb + (size_t)(n0 + prow + r * 32) * ldb + kb);
        asm volatile("cp.async.commit_group;");
    };

    issue(0, 0);
    issue(1, 1);

    int st = 0;
#pragma unroll 1
    for (int kt = 0; kt < KT; ++kt) {
        if (kt < KT - 1) asm volatile("cp.async.wait_group 1;");
        else             asm volatile("cp.async.wait_group 0;");
        __syncthreads();

        if (kt + 2 < KT) {
            int stw = st + 2; if (stw >= NSTAGE) stw -= NSTAGE;
            issue(kt + 2, stw);
        }

        const uint32_t aSt = aBase + st * STG_B;
        const uint32_t bSt = bBase + st * STG_B;

#pragma unroll
        for (int ks = 0; ks < 4; ++ks) {
            const uint32_t ko = ks * 32;
            uint32_t af[2][4], bf[4][2];
#pragma unroll
            for (int im = 0; im < 2; im++)
                LDSM4(af[im][0], af[im][1], af[im][2], af[im][3],
                      aSt + im * (16 * ROWB) + ko);
#pragma unroll
            for (int p = 0; p < 2; p++)
                LDSM4(bf[2 * p][0], bf[2 * p][1], bf[2 * p + 1][0], bf[2 * p + 1][1],
                      bSt + p * (16 * ROWB) + ko);
#pragma unroll
            for (int im = 0; im < 2; im++)
#pragma unroll
                for (int in_ = 0; in_ < 4; in_++)
                    MMA_F16(acc[im][in_], af[im], bf[in_]);
        }
        if (++st >= NSTAGE) st = 0;
    }
    __syncthreads();

    const float alpha = J->alpha;
#pragma unroll
    for (int im = 0; im < 2; im++) {
        const int r = m0 + wm * 32 + im * 16 + gid;
#pragma unroll
        for (int in_ = 0; in_ < 4; in_++) {
            const int col = n0 + wn * 32 + in_ * 8 + 2 * tig;
            epi_store(J, tz, r, col,
                      alpha * acc[im][in_][0], alpha * acc[im][in_][1],
                      alpha * acc[im][in_][2], alpha * acc[im][in_][3]);
        }
    }
}

// ---------------------------------------------------------------------------
// Persistent driver over up to two jobs' tile pools
// ---------------------------------------------------------------------------
__global__ __launch_bounds__(256, 2) void gemm_persist(Job j0, Job j1,
                                                       int njobs, int ctr_idx)
{
    extern __shared__ __half smem[];
    __shared__ unsigned s_t;
    const int tid = threadIdx.x;
    const unsigned total = (unsigned)(j0.ntiles + (njobs > 1 ? j1.ntiles : 0));

#pragma unroll 1
    while (true) {
        if (tid == 0) s_t = atomicAdd(&g_ctrs[ctr_idx], 1u);
        __syncthreads();
        unsigned t = s_t;
        if (t >= total) return;

        const Job* J = &j0;
        if (t >= (unsigned)j0.ntiles) { J = &j1; t -= (unsigned)j0.ntiles; }
        const unsigned per = (unsigned)(J->nx * J->ny);
        const int tz = (int)(t / per);
        const unsigned rr = t - (unsigned)tz * per;
        const int ty = (int)(rr / (unsigned)J->nx);
        const int tx = (int)(rr - (unsigned)ty * (unsigned)J->nx);

        if (J->mode & 8) tile64(J, tx, ty, tz, smem, tid);
        else             tile128(J, tx, ty, tz, smem, tid);
    }
}

// ---------------------------------------------------------------------------
__global__ void cvt_x(const float4* __restrict__ in, __half2* __restrict__ out)
{
    const int i = (blockIdx.x * blockDim.x + threadIdx.x) * 2;
    float4 a = in[i], b = in[i + 1];
    out[2 * i]     = __floats2half2_rn(a.x, a.y);
    out[2 * i + 1] = __floats2half2_rn(a.z, a.w);
    out[2 * i + 2] = __floats2half2_rn(b.x, b.y);
    out[2 * i + 3] = __floats2half2_rn(b.z, b.w);
}

__global__ void cvt_w3(const float4* __restrict__ w0, const float4* __restrict__ w1,
                       const float4* __restrict__ w2, __half2* __restrict__ out)
{
    const float4* src = (blockIdx.y == 0) ? w0 : ((blockIdx.y == 1) ? w1 : w2);
    __half2* dst = out + (size_t)blockIdx.y * (F_ * F_ / 2);
    const int i = blockIdx.x * blockDim.x + threadIdx.x;
    float4 v = src[i];
    dst[2 * i]     = __floats2half2_rn(v.x, v.y);
    dst[2 * i + 1] = __floats2half2_rn(v.z, v.w);
}

// ---------------------------------------------------------------------------
__global__ __launch_bounds__(256) void softmax2048h(__half2* __restrict__ S)
{
    __half2* p = S + ((size_t)blockIdx.y * T_ + blockIdx.x) * (T_ / 2);
    const int tid = threadIdx.x;
    __shared__ float rmax[8], rsum[8];

    float2 v[4];
    float m = -3.0e38f;
#pragma unroll
    for (int i = 0; i < 4; i++) {
        v[i] = __half22float2(p[tid + (i << 8)]);
        m = fmaxf(m, fmaxf(v[i].x, v[i].y));
    }
#pragma unroll
    for (int o = 16; o > 0; o >>= 1) m = fmaxf(m, __shfl_xor_sync(0xffffffffu, m, o));
    if ((tid & 31) == 0) rmax[tid >> 5] = m;
    __syncthreads();
    float bm = rmax[0];
#pragma unroll
    for (int i = 1; i < 8; i++) bm = fmaxf(bm, rmax[i]);

    float s = 0.0f;
#pragma unroll
    for (int i = 0; i < 4; i++) {
        v[i].x = __expf(v[i].x - bm); v[i].y = __expf(v[i].y - bm);
        s += v[i].x + v[i].y;
    }
#pragma unroll
    for (int o = 16; o > 0; o >>= 1) s += __shfl_xor_sync(0xffffffffu, s, o);
    if ((tid & 31) == 0) rsum[tid >> 5] = s;
    __syncthreads();
    float bs = 0.0f;
#pragma unroll
    for (int i = 0; i < 8; i++) bs += rsum[i];

    const float inv = 1.0f / bs;
#pragma unroll
    for (int i = 0; i < 4; i++)
        p[tid + (i << 8)] = __floats2half2_rn(v[i].x * inv, v[i].y * inv);
}

// ---------------------------------------------------------------------------
extern "C" void kernel_launch(void* const* d_in, const int* in_sizes, int n_in,
                              void* d_out, int out_size)
{
    const float* X  = (const float*)d_in[0];
    const float* Wq = (const float*)d_in[1];
    const float* bq = (const float*)d_in[2];
    const float* Wk = (const float*)d_in[3];
    const float* bk = (const float*)d_in[4];
    const float* Wv = (const float*)d_in[5];
    const float* bv = (const float*)d_in[6];
    float* O = (float*)d_out;

    __half *Xh, *Wcat, *QKh, *VTh, *Sh;
    float* bcat;
    unsigned* ctrs;
    cudaGetSymbolAddress((void**)&Xh,   g_Xh);
    cudaGetSymbolAddress((void**)&Wcat, g_Wcat);
    cudaGetSymbolAddress((void**)&bcat, g_bcat);
    cudaGetSymbolAddress((void**)&QKh,  g_QKh);
    cudaGetSymbolAddress((void**)&VTh,  g_VTh);
    cudaGetSymbolAddress((void**)&Sh,   g_Sh);
    cudaGetSymbolAddress((void**)&ctrs, g_ctrs);

    cudaFuncSetAttribute(gemm_persist,
                         cudaFuncAttributeMaxDynamicSharedMemorySize, GEMM_SMEM);

    int sms = 148;
    cudaDeviceGetAttribute(&sms, cudaDevAttrMultiProcessorCount, 0);
    const int PGRID = 2 * sms;

    cudaMemsetAsync(ctrs, 0, 4 * sizeof(unsigned));

    cvt_x<<<B_ * T_ * F_ / (256 * 8), 256>>>((const float4*)X, (__half2*)Xh);
    cvt_w3<<<dim3(F_ * F_ / (256 * 4), 3), 256>>>(
        (const float4*)Wq, (const float4*)Wk, (const float4*)Wv, (__half2*)Wcat);
    cudaMemcpyAsync(bcat,      bq, F_ * sizeof(float), cudaMemcpyDeviceToDevice);
    cudaMemcpyAsync(bcat + F_, bk, F_ * sizeof(float), cudaMemcpyDeviceToDevice);

    // ---- launch A: fused QK projection + direct-VT projection ----
    Job jQK = {};
    jQK.A = Xh;  jQK.B = Wcat; jQK.C = QKh; jQK.bias = bcat;
    jQK.N = 2 * F_; jQK.K = F_; jQK.lda = F_; jQK.ldb = F_; jQK.ldc = 2 * F_;
    jQK.bsA = 0; jQK.bsB = 0; jQK.bsC = 0;
    jQK.alpha = 1.0f; jQK.nx = 16; jQK.ny = 128; jQK.ntiles = 2048;
    jQK.mode = 1 | 4;

    Job jVT = {};
    jVT.A = Wcat + (size_t)2 * F_ * F_;  jVT.B = Xh;  jVT.C = VTh;  jVT.bias = bv;
    jVT.N = T_; jVT.K = F_; jVT.lda = F_; jVT.ldb = F_; jVT.ldc = T_;
    jVT.bsA = 0; jVT.bsB = (long long)T_ * F_; jVT.bsC = (long long)F_ * T_;
    jVT.alpha = 1.0f; jVT.nx = 16; jVT.ny = 8; jVT.ntiles = 8 * 16 * 8;
    jVT.mode = 2 | 4;

    gemm_persist<<<PGRID, 256, GEMM_SMEM>>>(jQK, jVT, 2, 0);

    // ---- launch B: scores S = (Q K^T)/32 ----
    Job jS = {};
    jS.A = QKh;  jS.B = QKh + F_;  jS.C = Sh;  jS.bias = nullptr;
    jS.N = T_; jS.K = F_; jS.lda = 2 * F_; jS.ldb = 2 * F_; jS.ldc = T_;
    jS.bsA = (long long)T_ * 2 * F_; jS.bsB = (long long)T_ * 2 * F_;
    jS.bsC = (long long)T_ * T_;
    jS.alpha = 0.03125f; jS.nx = 16; jS.ny = 16; jS.ntiles = 8 * 16 * 16;
    jS.mode = 4;

    gemm_persist<<<PGRID, 256, GEMM_SMEM>>>(jS, jS, 1, 1);

    softmax2048h<<<dim3(T_, B_), 256>>>((__half2*)Sh);

    // ---- launch C: O = P @ VT^T (fp32 out), BM=64 tiles for tail ----
    Job jO = {};
    jO.A = Sh;  jO.B = VTh;  jO.C = O;  jO.bias = nullptr;
    jO.N = F_; jO.K = T_; jO.lda = T_; jO.ldb = T_; jO.ldc = F_;
    jO.bsA = (long long)T_ * T_; jO.bsB = (long long)F_ * T_;
    jO.bsC = (long long)T_ * F_;
    jO.alpha = 1.0f; jO.nx = 8; jO.ny = 32; jO.ntiles = 8 * 32 * 8;
    jO.mode = 8;

    gemm_persist<<<PGRID, 256, GEMM_SMEM>>>(jO, jO, 1, 2);
}